// round 5
// baseline (speedup 1.0000x reference)
#include <cuda_runtime.h>

#define B_  32
#define N_  512
#define C_  1024
#define H_  16
#define HD_ 64

// Scratch (allocation-free rule: __device__ globals)
__device__ float g_q [(size_t)B_*H_*N_*HD_];
__device__ float g_k [(size_t)B_*H_*N_*HD_];
__device__ float g_v [(size_t)B_*H_*N_*HD_];
__device__ float g_ao[(size_t)B_*N_*C_];

// ---------------------------------------------------------------------------
// GEMM core: C_tile[128x128] = A[128x1024] * Bw[128x1024]^T  (both K-inner,
// row stride 1024). 256 threads, 8x8 per thread, BK=8, global prefetch.
// ---------------------------------------------------------------------------
__device__ __forceinline__ void gemm_core(const float* __restrict__ A,
                                          const float* __restrict__ Bw,
                                          float (&c)[8][8])
{
    __shared__ float As[8][128];
    __shared__ float Bs[8][128];
    const int tid = threadIdx.x;
    const int row = tid >> 1;          // 0..127
    const int seg = (tid & 1) << 2;    // 0 or 4
    const int tx  = tid & 15;
    const int ty  = tid >> 4;

    const float* Ap = A  + (size_t)row * 1024 + seg;
    const float* Bp = Bw + (size_t)row * 1024 + seg;

    #pragma unroll
    for (int i = 0; i < 8; i++)
        #pragma unroll
        for (int j = 0; j < 8; j++) c[i][j] = 0.f;

    float4 av = *(const float4*)(Ap);
    float4 bv = *(const float4*)(Bp);

    for (int k0 = 0; k0 < 1024; k0 += 8) {
        __syncthreads();
        As[seg+0][row]=av.x; As[seg+1][row]=av.y; As[seg+2][row]=av.z; As[seg+3][row]=av.w;
        Bs[seg+0][row]=bv.x; Bs[seg+1][row]=bv.y; Bs[seg+2][row]=bv.z; Bs[seg+3][row]=bv.w;
        __syncthreads();
        if (k0 + 8 < 1024) {            // prefetch next K-tile (hides L2 latency)
            av = *(const float4*)(Ap + k0 + 8);
            bv = *(const float4*)(Bp + k0 + 8);
        }
        #pragma unroll
        for (int kk = 0; kk < 8; kk++) {
            float a[8], b[8];
            *(float4*)(a)     = *(const float4*)(&As[kk][ty*8]);
            *(float4*)(a + 4) = *(const float4*)(&As[kk][ty*8 + 4]);
            *(float4*)(b)     = *(const float4*)(&Bs[kk][tx*8]);
            *(float4*)(b + 4) = *(const float4*)(&Bs[kk][tx*8 + 4]);
            #pragma unroll
            for (int i = 0; i < 8; i++)
                #pragma unroll
                for (int j = 0; j < 8; j++)
                    c[i][j] = fmaf(a[i], b[j], c[i][j]);
        }
    }
}

// ---------------------------------------------------------------------------
// Kernel 1: qkv = x @ W_qkv^T, scattered into q(*SCALE)/k/v as [B,H,N,HD]
// grid = (3072/128=24, 16384/128=128)
// ---------------------------------------------------------------------------
__global__ __launch_bounds__(256) void qkv_kernel(const float* __restrict__ X,
                                                  const float* __restrict__ W)
{
    float c[8][8];
    gemm_core(X + (size_t)blockIdx.y * 128 * 1024,
              W + (size_t)blockIdx.x * 128 * 1024, c);

    const int tx = threadIdx.x & 15, ty = threadIdx.x >> 4;
    const int m0 = blockIdx.y * 128 + ty * 8;
    const int n0 = blockIdx.x * 128 + tx * 8;
    #pragma unroll
    for (int i = 0; i < 8; i++) {
        const int m  = m0 + i;
        const int b  = m >> 9;        // N_=512
        const int nn = m & 511;
        #pragma unroll
        for (int j = 0; j < 8; j++) {
            const int n   = n0 + j;
            const int s   = n >> 10;         // 0=q,1=k,2=v
            const int rem = n & 1023;
            const int h   = rem >> 6;
            const int hd  = rem & 63;
            const size_t idx = (((size_t)(b * H_ + h) * N_ + nn) * HD_ + hd);
            if      (s == 0) g_q[idx] = c[i][j] * 0.125f;   // SCALE = 64^-0.5
            else if (s == 1) g_k[idx] = c[i][j];
            else             g_v[idx] = c[i][j];
        }
    }
}

// ---------------------------------------------------------------------------
// Kernel 2: flash attention. One block = (64 q-rows) x (one b,h).
// Online softmax over 8 K/V tiles of 64. Only the column mask bias matters
// (row bias is a per-row softmax shift => cancels exactly).
// grid = (8, 512), 256 threads, dynamic smem.
// ---------------------------------------------------------------------------
#define ATTN_SMEM_FLOATS (64*68 /*Qt*/ + 64*68 /*Kt*/ + 64*64 /*Vs*/ + 64*68 /*Ss*/ \
                          + 64 /*ms*/ + 256 /*red*/ + 64 /*mrow*/ + 64 /*lrow*/ + 64 /*srow*/)
#define ATTN_SMEM_BYTES  (ATTN_SMEM_FLOATS * 4)

__global__ __launch_bounds__(256) void attn_kernel(const float* __restrict__ mask)
{
    extern __shared__ float sm[];
    float* Qt   = sm;                // [64][68]  d-major (transposed)
    float* Kt   = Qt + 64*68;        // [64][68]  d-major (transposed)
    float* Vs   = Kt + 64*68;        // [64][64]  k-major
    float* Ss   = Vs + 64*64;        // [64][68]  scores / P
    float* ms   = Ss + 64*68;        // [64]      mask col bias
    float* red  = ms + 64;           // [64][4]   reduction scratch
    float* mrow = red + 256;         // [64] running max
    float* lrow = mrow + 64;         // [64] running sum
    float* srow = lrow + 64;         // [64] rescale factor

    const int tid = threadIdx.x;
    const int bh  = blockIdx.y;
    const int b   = bh >> 4;
    const int h   = bh & 15;
    const int q0  = blockIdx.x << 6;

    const float* Qg = g_q + ((size_t)bh * N_ + q0) * HD_;
    const float* Kg = g_k + (size_t)bh * N_ * HD_;
    const float* Vg = g_v + (size_t)bh * N_ * HD_;
    const float* Mg = mask + (size_t)b * N_;

    // Load Q tile transposed (d-major) — avoids column bank conflicts in S gemm
    for (int t = tid; t < 1024; t += 256) {
        const int r  = t >> 4;
        const int cs = (t & 15) << 2;
        float4 qv = *(const float4*)(Qg + r * 64 + cs);
        Qt[(cs+0)*68 + r] = qv.x;
        Qt[(cs+1)*68 + r] = qv.y;
        Qt[(cs+2)*68 + r] = qv.z;
        Qt[(cs+3)*68 + r] = qv.w;
    }
    if (tid < 64) { mrow[tid] = -1e30f; lrow[tid] = 0.f; }

    float o[4][4];
    #pragma unroll
    for (int i = 0; i < 4; i++)
        #pragma unroll
        for (int j = 0; j < 4; j++) o[i][j] = 0.f;

    const int tq = tid >> 4;      // 0..15 (q micro-row group)
    const int tk = tid & 15;      // 0..15 (k / d micro-col group)
    const int r  = tid >> 2;      // 0..63 (softmax row)
    const int sg = tid & 3;       // 0..3  (16-col segment)

    for (int kt = 0; kt < 8; kt++) {
        __syncthreads();          // prior-iter reads of Kt/Vs/Ss done
        const float* Kp = Kg + kt * 64 * 64;
        for (int t = tid; t < 1024; t += 256) {
            const int rr = t >> 4;
            const int cs = (t & 15) << 2;
            float4 kv = *(const float4*)(Kp + rr * 64 + cs);
            Kt[(cs+0)*68 + rr] = kv.x;
            Kt[(cs+1)*68 + rr] = kv.y;
            Kt[(cs+2)*68 + rr] = kv.z;
            Kt[(cs+3)*68 + rr] = kv.w;
        }
        const float4* Vp = (const float4*)(Vg + kt * 64 * 64);
        for (int t = tid; t < 1024; t += 256) ((float4*)Vs)[t] = Vp[t];
        if (tid < 64) ms[tid] = Mg[kt * 64 + tid];
        __syncthreads();

        // S = Q K^T  (64x64 tile, 4x4 per thread)
        float s[4][4];
        #pragma unroll
        for (int i = 0; i < 4; i++)
            #pragma unroll
            for (int j = 0; j < 4; j++) s[i][j] = 0.f;
        #pragma unroll 4
        for (int d = 0; d < 64; d++) {
            float4 qa = *(const float4*)(&Qt[d*68 + (tq<<2)]);
            float4 kb = *(const float4*)(&Kt[d*68 + (tk<<2)]);
            const float aa[4] = {qa.x, qa.y, qa.z, qa.w};
            const float bb[4] = {kb.x, kb.y, kb.z, kb.w};
            #pragma unroll
            for (int i = 0; i < 4; i++)
                #pragma unroll
                for (int j = 0; j < 4; j++)
                    s[i][j] = fmaf(aa[i], bb[j], s[i][j]);
        }
        #pragma unroll
        for (int i = 0; i < 4; i++)
            #pragma unroll
            for (int j = 0; j < 4; j++)
                Ss[(tq*4 + i)*68 + tk*4 + j] = s[i][j] + ms[tk*4 + j];
        __syncthreads();

        // Online softmax: 4 threads per row, 16 cols each
        float* Sr = Ss + r*68 + sg*16;
        float lm = -1e30f;
        #pragma unroll
        for (int j2 = 0; j2 < 16; j2++) lm = fmaxf(lm, Sr[j2]);
        red[(r<<2) + sg] = lm;
        __syncthreads();
        const float tmax  = fmaxf(fmaxf(red[r<<2], red[(r<<2)+1]),
                                  fmaxf(red[(r<<2)+2], red[(r<<2)+3]));
        const float mprev = mrow[r];
        const float mnew  = fmaxf(mprev, tmax);
        float lsum = 0.f;
        #pragma unroll
        for (int j2 = 0; j2 < 16; j2++) {
            const float p = __expf(Sr[j2] - mnew);
            Sr[j2] = p;
            lsum += p;
        }
        __syncthreads();          // max reads done before red reuse
        red[(r<<2) + sg] = lsum;
        __syncthreads();
        if (sg == 0) {
            const float ts = red[r<<2] + red[(r<<2)+1] + red[(r<<2)+2] + red[(r<<2)+3];
            const float sc = __expf(mprev - mnew);   // 0 on first tile
            lrow[r] = lrow[r] * sc + ts;
            mrow[r] = mnew;
            srow[r] = sc;
        }
        __syncthreads();

        // O = O*scale + P @ V   (4x4 per thread over (q,d))
        float scl[4];
        #pragma unroll
        for (int i = 0; i < 4; i++) scl[i] = srow[tq*4 + i];
        #pragma unroll
        for (int i = 0; i < 4; i++)
            #pragma unroll
            for (int j = 0; j < 4; j++) o[i][j] *= scl[i];
        #pragma unroll 4
        for (int kk = 0; kk < 64; kk++) {
            float4 vb = *(const float4*)(&Vs[kk*64 + (tk<<2)]);
            const float vv[4] = {vb.x, vb.y, vb.z, vb.w};
            float pv[4];
            #pragma unroll
            for (int i = 0; i < 4; i++) pv[i] = Ss[(tq*4 + i)*68 + kk];
            #pragma unroll
            for (int i = 0; i < 4; i++)
                #pragma unroll
                for (int j = 0; j < 4; j++)
                    o[i][j] = fmaf(pv[i], vv[j], o[i][j]);
        }
    }

    // Epilogue: O /= l, write [B,N,C] with c = h*64 + d
    #pragma unroll
    for (int i = 0; i < 4; i++) {
        const float inv = 1.f / lrow[tq*4 + i];
        const int qg = q0 + tq*4 + i;
        float4 ov;
        ov.x = o[i][0]*inv; ov.y = o[i][1]*inv; ov.z = o[i][2]*inv; ov.w = o[i][3]*inv;
        *(float4*)(g_ao + ((size_t)(b*N_ + qg) * C_ + h*64 + (tk<<2))) = ov;
    }
}

// ---------------------------------------------------------------------------
// Kernel 3: out = attn_out @ W_proj^T + b_proj. grid = (8, 128)
// ---------------------------------------------------------------------------
__global__ __launch_bounds__(256) void proj_kernel(const float* __restrict__ Wp,
                                                   const float* __restrict__ bias,
                                                   float* __restrict__ out)
{
    float c[8][8];
    gemm_core(g_ao + (size_t)blockIdx.y * 128 * 1024,
              Wp   + (size_t)blockIdx.x * 128 * 1024, c);

    const int tx = threadIdx.x & 15, ty = threadIdx.x >> 4;
    const int m0 = blockIdx.y * 128 + ty * 8;
    const int n0 = blockIdx.x * 128 + tx * 8;
    #pragma unroll
    for (int i = 0; i < 8; i++) {
        float* op = out + (size_t)(m0 + i) * 1024 + n0;
        float4 v0, v1;
        v0.x = c[i][0] + bias[n0+0]; v0.y = c[i][1] + bias[n0+1];
        v0.z = c[i][2] + bias[n0+2]; v0.w = c[i][3] + bias[n0+3];
        v1.x = c[i][4] + bias[n0+4]; v1.y = c[i][5] + bias[n0+5];
        v1.z = c[i][6] + bias[n0+6]; v1.w = c[i][7] + bias[n0+7];
        *(float4*)(op)     = v0;
        *(float4*)(op + 4) = v1;
    }
}

// ---------------------------------------------------------------------------
extern "C" void kernel_launch(void* const* d_in, const int* in_sizes, int n_in,
                              void* d_out, int out_size)
{
    const float* x     = (const float*)d_in[0];
    const float* mask  = (const float*)d_in[1];
    const float* Wqkv  = (const float*)d_in[2];
    const float* Wproj = (const float*)d_in[3];
    const float* bproj = (const float*)d_in[4];
    float* out = (float*)d_out;

    cudaFuncSetAttribute(attn_kernel, cudaFuncAttributeMaxDynamicSharedMemorySize,
                         ATTN_SMEM_BYTES);

    qkv_kernel <<<dim3(24, 128), 256>>>(x, Wqkv);
    attn_kernel<<<dim3(8, 512), 256, ATTN_SMEM_BYTES>>>(mask);
    proj_kernel<<<dim3(8, 128), 256>>>(Wproj, bproj, out);
}